// round 12
// baseline (speedup 1.0000x reference)
#include <cuda_runtime.h>
#include <cuda_fp16.h>
#include <cstdint>
#include <cstddef>

#define B_   512
#define IN_  4096
#define OUT_ 11008

#define MT      512
#define NT      64
#define NTILES  172          // OUT / NT
#define KSPLIT  4
#define KPART   1024         // IN / KSPLIT
#define BK      64
#define NCH     16           // KPART / BK
#define PLANE   ((size_t)B_ * OUT_)

// static device scratch (no runtime allocation)
__device__ __align__(1024) __half g_x[(size_t)B_ * IN_];
__device__ __align__(1024) float  g_part[KSPLIT * PLANE];   // 90 MB partials
__device__ unsigned g_sem[NTILES];

// ---------------- helpers ----------------------------------------------------
__device__ __forceinline__ uint32_t smem_u32(const void* p) {
    uint32_t a;
    asm("{ .reg .u64 t; cvta.to.shared.u64 t, %1; cvt.u32.u64 %0, t; }"
        : "=r"(a) : "l"(p));
    return a;
}
#define CP16(dst, src) \
    asm volatile("cp.async.cg.shared.global [%0], [%1], 16;" :: "r"(dst), "l"(src))
#define CP_COMMIT() asm volatile("cp.async.commit_group;" ::: "memory")

__device__ __forceinline__ void ldsm_x4(uint32_t* r, uint32_t addr) {
    asm volatile("ldmatrix.sync.aligned.m8n8.x4.shared.b16 {%0,%1,%2,%3}, [%4];"
                 : "=r"(r[0]), "=r"(r[1]), "=r"(r[2]), "=r"(r[3]) : "r"(addr));
}
__device__ __forceinline__ void mma16816(float* c, const uint32_t* a, const uint32_t* b) {
    asm volatile(
        "mma.sync.aligned.m16n8k16.row.col.f32.f16.f16.f32 "
        "{%0,%1,%2,%3}, {%4,%5,%6,%7}, {%8,%9}, {%0,%1,%2,%3};\n"
        : "+f"(c[0]), "+f"(c[1]), "+f"(c[2]), "+f"(c[3])
        : "r"(a[0]), "r"(a[1]), "r"(a[2]), "r"(a[3]), "r"(b[0]), "r"(b[1]));
}

// ---------------- kernel 1: x fp32 -> fp16 + semaphore reset -----------------
__global__ void xconv_kernel(const float* __restrict__ x) {
    if (blockIdx.x == 0 && threadIdx.x < NTILES) g_sem[threadIdx.x] = 0u;
    const int n4 = (B_ * IN_) / 4;
    int stride = gridDim.x * blockDim.x;
    for (int i = blockIdx.x * blockDim.x + threadIdx.x; i < n4; i += stride) {
        float4 v = reinterpret_cast<const float4*>(x)[i];
        __half2 lo = __floats2half2_rn(v.x, v.y);
        __half2 hi = __floats2half2_rn(v.z, v.w);
        uint2 o;
        o.x = *reinterpret_cast<uint32_t*>(&lo);
        o.y = *reinterpret_cast<uint32_t*>(&hi);
        reinterpret_cast<uint2*>(g_x)[i] = o;
    }
}

// ---------------- fused dequant + GEMM + inline split-K reduce ---------------
// Tile: M=512, N=64, K=1024. Grid = 172 x 4. 3-stage XOR-swizzled smem pipe.
// Swizzle: 128B rows, 16B chunk c16' = c16 ^ (row & 7).
static constexpr uint32_t ASZ = MT * 128;            // 65536 per stage
static constexpr uint32_t BSZ = NT * 128;            // 8192 per stage
// 3*ASZ + 3*BSZ tiles, then 2048B LUT, then 16B for s_last.
static constexpr uint32_t SMEM_REQ = 3 * ASZ + 3 * BSZ + 2048 + 16;  // 223248

__global__ void __launch_bounds__(512, 1)
fused_kernel(const int* __restrict__ stored, const int* __restrict__ sign,
             const float* __restrict__ lmin_p, const float* __restrict__ lmax_p,
             const float* __restrict__ bias, const float* __restrict__ scale,
             float* __restrict__ out) {
    extern __shared__ char smem[];
    const uint32_t sA0 = smem_u32(smem);
    const uint32_t sB0 = sA0 + 3 * ASZ;
    unsigned* lut    = reinterpret_cast<unsigned*>(smem + 3 * ASZ + 3 * BSZ);
    unsigned* s_last = reinterpret_cast<unsigned*>(smem + 3 * ASZ + 3 * BSZ + 2048);

    const int tid  = threadIdx.x;
    const int wid  = tid >> 5;
    const int lane = tid & 31;
    const int ntile = blockIdx.x % NTILES;
    const int kq    = blockIdx.x / NTILES;
    const int n0    = ntile * NT;
    const int k0    = kq * KPART;

    // ---- build LUT ----
    {
        float lmin = __ldg(lmin_p);
        float lmax = __ldg(lmax_p);
        if (tid < 511) {
            int s = tid - 255;
            int mag = s < 0 ? -s : s;
            float w = 0.0f;
            if (s != 0) {
                float nrm = (255.0f - (float)mag) * (1.0f / 254.0f);
                w = expf(lmin + nrm * (lmax - lmin));
                if (s < 0) w = -w;
            }
            unsigned hb = (unsigned)__half_as_ushort(__float2half_rn(w));
            lut[tid] = hb | (hb << 16);
        }
    }
    __syncthreads();

    // ---- A fill geometry: 8 x 16B chunks per thread, swizzled ----
    int arow[8];
    uint32_t adoff[8];
    int asrc[8];
#pragma unroll
    for (int j = 0; j < 8; j++) {
        int idx = j * 512 + tid;          // 0..4095
        int row = idx >> 3;
        int c16 = idx & 7;
        arow[j] = row;
        asrc[j] = c16 * 8;
        adoff[j] = (uint32_t)(row * 128 + ((c16 ^ (row & 7)) << 4));
    }
    auto fillA = [&](int chunk, uint32_t aStage) {
        const __half* base = g_x + k0 + chunk * BK;
#pragma unroll
        for (int j = 0; j < 8; j++)
            CP16(aStage + adoff[j], base + (size_t)arow[j] * IN_ + asrc[j]);
        CP_COMMIT();
    };

    // ---- B dequant: 8 elems (one 16B chunk) per thread ----
    const int drow = tid >> 3;
    const int dc16 = tid & 7;
    const int* stp = stored + (size_t)(n0 + drow) * IN_ + k0 + dc16 * 8;
    const int* sgp = sign   + (size_t)(n0 + drow) * IN_ + k0 + dc16 * 8;
    const uint32_t bdoff = (uint32_t)(drow * 128 + ((dc16 ^ (drow & 7)) << 4));

    int4 st0, st1, sg0, sg1;
    auto bLDG = [&](int chunk) {
        const int4* a = reinterpret_cast<const int4*>(stp + chunk * BK);
        const int4* b = reinterpret_cast<const int4*>(sgp + chunk * BK);
        st0 = a[0]; st1 = a[1];
        sg0 = b[0]; sg1 = b[1];
    };
    auto bSTS = [&](uint32_t bStage) {
        unsigned l0 = lut[sg0.x * st0.x + 255];
        unsigned l1 = lut[sg0.y * st0.y + 255];
        unsigned l2 = lut[sg0.z * st0.z + 255];
        unsigned l3 = lut[sg0.w * st0.w + 255];
        unsigned l4 = lut[sg1.x * st1.x + 255];
        unsigned l5 = lut[sg1.y * st1.y + 255];
        unsigned l6 = lut[sg1.z * st1.z + 255];
        unsigned l7 = lut[sg1.w * st1.w + 255];
        uint32_t w0 = __byte_perm(l0, l1, 0x5410);
        uint32_t w1 = __byte_perm(l2, l3, 0x5410);
        uint32_t w2 = __byte_perm(l4, l5, 0x5410);
        uint32_t w3 = __byte_perm(l6, l7, 0x5410);
        asm volatile("st.shared.v4.b32 [%0], {%1,%2,%3,%4};"
                     :: "r"(bStage + bdoff), "r"(w0), "r"(w1), "r"(w2), "r"(w3)
                     : "memory");
    };

    // ---- ldmatrix offsets (16 warps: wm 0..7 x 64 rows, wn 0..1 x 32 cols) --
    const int wm = wid >> 1;
    const int wn = wid & 1;
    const int lr = lane & 7;
    const int lj = lane >> 3;
    uint32_t aOff[4][4], bOff[4][2];
#pragma unroll
    for (int ks = 0; ks < 4; ks++) {
#pragma unroll
        for (int mf = 0; mf < 4; mf++) {
            int row = wm * 64 + mf * 16 + lr + (lj & 1) * 8;
            int c16 = 2 * ks + (lj >> 1);
            aOff[ks][mf] = (uint32_t)(row * 128 + ((c16 ^ lr) << 4));
        }
#pragma unroll
        for (int nh = 0; nh < 2; nh++) {
            int nrow = wn * 32 + nh * 16 + lr + (lj >> 1) * 8;
            int c16  = 2 * ks + (lj & 1);
            bOff[ks][nh] = (uint32_t)(nrow * 128 + ((c16 ^ lr) << 4));
        }
    }

    float acc[4][4][4];
#pragma unroll
    for (int a = 0; a < 4; a++)
#pragma unroll
        for (int b = 0; b < 4; b++)
#pragma unroll
            for (int q = 0; q < 4; q++) acc[a][b][q] = 0.0f;

    // ---- prologue ----
    bLDG(0); bSTS(sB0);
    bLDG(1); bSTS(sB0 + BSZ);
    fillA(0, sA0);
    fillA(1, sA0 + ASZ);

    // ---- main loop ----
    int s = 0;
    for (int i = 0; i < NCH; i++) {
        const int t = (s + 2 >= 3) ? s - 1 : s + 2;   // (i+2)%3
        if (i < NCH - 1) asm volatile("cp.async.wait_group 1;" ::: "memory");
        else             asm volatile("cp.async.wait_group 0;" ::: "memory");
        __syncthreads();

        const bool refill = (i + 2 < NCH);
        if (refill) {
            bLDG(i + 2);
            fillA(i + 2, sA0 + t * ASZ);
        }

        uint32_t aBase = sA0 + s * ASZ;
        uint32_t bBase = sB0 + s * BSZ;
#pragma unroll
        for (int ks = 0; ks < 4; ks++) {
            uint32_t a_frag[4][4];
            uint32_t b_frag[4][2];
#pragma unroll
            for (int mf = 0; mf < 4; mf++)
                ldsm_x4(a_frag[mf], aBase + aOff[ks][mf]);
#pragma unroll
            for (int nh = 0; nh < 2; nh++) {
                uint32_t r[4];
                ldsm_x4(r, bBase + bOff[ks][nh]);
                b_frag[2 * nh][0]     = r[0];
                b_frag[2 * nh][1]     = r[1];
                b_frag[2 * nh + 1][0] = r[2];
                b_frag[2 * nh + 1][1] = r[3];
            }
#pragma unroll
            for (int mf = 0; mf < 4; mf++)
#pragma unroll
                for (int nf = 0; nf < 4; nf++)
                    mma16816(acc[mf][nf], a_frag[mf], b_frag[nf]);
        }

        if (refill) bSTS(sB0 + t * BSZ);

        if (++s == 3) s = 0;
    }

    // ---- store partial slab ----
    float* plane = g_part + (size_t)kq * PLANE;
    const int lq = lane >> 2;
    const int lp = lane & 3;
#pragma unroll
    for (int mf = 0; mf < 4; mf++) {
        int grow = wm * 64 + mf * 16 + lq;
#pragma unroll
        for (int nf = 0; nf < 4; nf++) {
            int gcol = n0 + wn * 32 + nf * 8 + 2 * lp;
            float* p = plane + (size_t)grow * OUT_ + gcol;
            float2 v0, v1;
            v0.x = acc[mf][nf][0];
            v0.y = acc[mf][nf][1];
            v1.x = acc[mf][nf][2];
            v1.y = acc[mf][nf][3];
            *reinterpret_cast<float2*>(p)            = v0;
            *reinterpret_cast<float2*>(p + 8 * OUT_) = v1;
        }
    }

    // ---- last CTA per ntile reduces the 4 partial slabs -> out --------------
    __threadfence();
    __syncthreads();
    if (tid == 0) *s_last = atomicAdd(&g_sem[ntile], 1u);
    __syncthreads();
    if (*s_last == KSPLIT - 1) {
        __threadfence();   // acquire: other CTAs' partial stores now visible
        const int row = tid;                   // 0..511
        const float* p0 = g_part + (size_t)row * OUT_ + n0;
        const float* p1 = p0 + PLANE;
        const float* p2 = p0 + 2 * PLANE;
        const float* p3 = p0 + 3 * PLANE;
        float* orow = out + (size_t)row * OUT_ + n0;
#pragma unroll
        for (int c = 0; c < NT; c += 4) {
            float4 a0 = __ldg(reinterpret_cast<const float4*>(p0 + c));
            float4 a1 = __ldg(reinterpret_cast<const float4*>(p1 + c));
            float4 a2 = __ldg(reinterpret_cast<const float4*>(p2 + c));
            float4 a3 = __ldg(reinterpret_cast<const float4*>(p3 + c));
            float4 bb = __ldg(reinterpret_cast<const float4*>(bias + n0 + c));
            float4 cc = __ldg(reinterpret_cast<const float4*>(scale + n0 + c));
            float4 r;
            r.x = (a0.x + a1.x + a2.x + a3.x + bb.x) * cc.x;
            r.y = (a0.y + a1.y + a2.y + a3.y + bb.y) * cc.y;
            r.z = (a0.z + a1.z + a2.z + a3.z + bb.z) * cc.z;
            r.w = (a0.w + a1.w + a2.w + a3.w + bb.w) * cc.w;
            *reinterpret_cast<float4*>(orow + c) = r;
        }
    }
}

// ---------------- launch -----------------------------------------------------
extern "C" void kernel_launch(void* const* d_in, const int* in_sizes, int n_in,
                              void* d_out, int out_size) {
    const float* x      = (const float*)d_in[0];
    const int*   stored = (const int*)d_in[1];
    const int*   sign   = (const int*)d_in[2];
    const float* lmin   = (const float*)d_in[3];
    const float* lmax   = (const float*)d_in[4];
    const float* scale  = (const float*)d_in[5];
    const float* bias   = (const float*)d_in[6];
    float* out = (float*)d_out;

    cudaFuncSetAttribute(fused_kernel, cudaFuncAttributeMaxDynamicSharedMemorySize,
                         (int)SMEM_REQ);

    xconv_kernel<<<512, 256>>>(x);
    fused_kernel<<<NTILES * KSPLIT, 512, SMEM_REQ>>>(stored, sign, lmin, lmax,
                                                     bias, scale, out);
}

// round 13
// speedup vs baseline: 1.4759x; 1.4759x over previous
#include <cuda_runtime.h>
#include <cuda_fp16.h>
#include <cstdint>
#include <cstddef>

#define B_   512
#define IN_  4096
#define OUT_ 11008

#define MT      512
#define NT      64
#define NTILES  172          // OUT / NT
#define KSPLIT  4
#define KPART   1024         // IN / KSPLIT
#define BK      64
#define NCH     16           // KPART / BK
#define PLANE   ((size_t)B_ * OUT_)

// static device scratch (no runtime allocation)
__device__ __align__(1024) __half g_x[(size_t)B_ * IN_];
__device__ __align__(1024) __half g_part[KSPLIT * PLANE];   // 45 MB fp16 partials

// ---------------- helpers ----------------------------------------------------
__device__ __forceinline__ uint32_t smem_u32(const void* p) {
    uint32_t a;
    asm("{ .reg .u64 t; cvta.to.shared.u64 t, %1; cvt.u32.u64 %0, t; }"
        : "=r"(a) : "l"(p));
    return a;
}
#define CP16(dst, src) \
    asm volatile("cp.async.cg.shared.global [%0], [%1], 16;" :: "r"(dst), "l"(src))
#define CP_COMMIT() asm volatile("cp.async.commit_group;" ::: "memory")

__device__ __forceinline__ void ldsm_x4(uint32_t* r, uint32_t addr) {
    asm volatile("ldmatrix.sync.aligned.m8n8.x4.shared.b16 {%0,%1,%2,%3}, [%4];"
                 : "=r"(r[0]), "=r"(r[1]), "=r"(r[2]), "=r"(r[3]) : "r"(addr));
}
__device__ __forceinline__ void mma16816(float* c, const uint32_t* a, const uint32_t* b) {
    asm volatile(
        "mma.sync.aligned.m16n8k16.row.col.f32.f16.f16.f32 "
        "{%0,%1,%2,%3}, {%4,%5,%6,%7}, {%8,%9}, {%0,%1,%2,%3};\n"
        : "+f"(c[0]), "+f"(c[1]), "+f"(c[2]), "+f"(c[3])
        : "r"(a[0]), "r"(a[1]), "r"(a[2]), "r"(a[3]), "r"(b[0]), "r"(b[1]));
}

// ---------------- kernel 1: x fp32 -> fp16 -----------------------------------
__global__ void xconv_kernel(const float* __restrict__ x) {
    const int n4 = (B_ * IN_) / 4;
    int stride = gridDim.x * blockDim.x;
    for (int i = blockIdx.x * blockDim.x + threadIdx.x; i < n4; i += stride) {
        float4 v = reinterpret_cast<const float4*>(x)[i];
        __half2 lo = __floats2half2_rn(v.x, v.y);
        __half2 hi = __floats2half2_rn(v.z, v.w);
        uint2 o;
        o.x = *reinterpret_cast<uint32_t*>(&lo);
        o.y = *reinterpret_cast<uint32_t*>(&hi);
        reinterpret_cast<uint2*>(g_x)[i] = o;
    }
}

// ---------------- fused dequant + GEMM kernel --------------------------------
// Tile: M=512, N=64, K=1024. Grid = 172 x 4. 3-stage XOR-swizzled smem pipe.
// Swizzle: 128B rows, 16B chunk c16' = c16 ^ (row & 7).
static constexpr uint32_t ASZ = MT * 128;            // 65536 per stage
static constexpr uint32_t BSZ = NT * 128;            // 8192 per stage
static constexpr uint32_t SMEM_REQ = 3 * ASZ + 3 * BSZ + 2048;  // 223232

__global__ void __launch_bounds__(512, 1)
fused_kernel(const int* __restrict__ stored, const int* __restrict__ sign,
             const float* __restrict__ lmin_p, const float* __restrict__ lmax_p) {
    extern __shared__ char smem[];
    const uint32_t sA0 = smem_u32(smem);
    const uint32_t sB0 = sA0 + 3 * ASZ;
    unsigned* lut = reinterpret_cast<unsigned*>(smem + 3 * ASZ + 3 * BSZ);

    const int tid  = threadIdx.x;
    const int wid  = tid >> 5;
    const int lane = tid & 31;
    const int ntile = blockIdx.x % NTILES;
    const int kq    = blockIdx.x / NTILES;
    const int n0    = ntile * NT;
    const int k0    = kq * KPART;

    // ---- build LUT ----
    {
        float lmin = __ldg(lmin_p);
        float lmax = __ldg(lmax_p);
        if (tid < 511) {
            int s = tid - 255;
            int mag = s < 0 ? -s : s;
            float w = 0.0f;
            if (s != 0) {
                float nrm = (255.0f - (float)mag) * (1.0f / 254.0f);
                w = expf(lmin + nrm * (lmax - lmin));
                if (s < 0) w = -w;
            }
            unsigned hb = (unsigned)__half_as_ushort(__float2half_rn(w));
            lut[tid] = hb | (hb << 16);
        }
    }
    __syncthreads();

    // ---- A fill geometry: 8 x 16B chunks per thread, swizzled ----
    int arow[8];
    uint32_t adoff[8];
    int asrc[8];
#pragma unroll
    for (int j = 0; j < 8; j++) {
        int idx = j * 512 + tid;          // 0..4095
        int row = idx >> 3;
        int c16 = idx & 7;
        arow[j] = row;
        asrc[j] = c16 * 8;
        adoff[j] = (uint32_t)(row * 128 + ((c16 ^ (row & 7)) << 4));
    }
    auto fillA = [&](int chunk, uint32_t aStage) {
        const __half* base = g_x + k0 + chunk * BK;
#pragma unroll
        for (int j = 0; j < 8; j++)
            CP16(aStage + adoff[j], base + (size_t)arow[j] * IN_ + asrc[j]);
        CP_COMMIT();
    };

    // ---- B dequant: 8 elems (one 16B chunk) per thread ----
    const int drow = tid >> 3;
    const int dc16 = tid & 7;
    const int* stp = stored + (size_t)(n0 + drow) * IN_ + k0 + dc16 * 8;
    const int* sgp = sign   + (size_t)(n0 + drow) * IN_ + k0 + dc16 * 8;
    const uint32_t bdoff = (uint32_t)(drow * 128 + ((dc16 ^ (drow & 7)) << 4));

    int4 st0, st1, sg0, sg1;
    auto bLDG = [&](int chunk) {
        const int4* a = reinterpret_cast<const int4*>(stp + chunk * BK);
        const int4* b = reinterpret_cast<const int4*>(sgp + chunk * BK);
        st0 = a[0]; st1 = a[1];
        sg0 = b[0]; sg1 = b[1];
    };
    auto bSTS = [&](uint32_t bStage) {
        unsigned l0 = lut[sg0.x * st0.x + 255];
        unsigned l1 = lut[sg0.y * st0.y + 255];
        unsigned l2 = lut[sg0.z * st0.z + 255];
        unsigned l3 = lut[sg0.w * st0.w + 255];
        unsigned l4 = lut[sg1.x * st1.x + 255];
        unsigned l5 = lut[sg1.y * st1.y + 255];
        unsigned l6 = lut[sg1.z * st1.z + 255];
        unsigned l7 = lut[sg1.w * st1.w + 255];
        uint32_t w0 = __byte_perm(l0, l1, 0x5410);
        uint32_t w1 = __byte_perm(l2, l3, 0x5410);
        uint32_t w2 = __byte_perm(l4, l5, 0x5410);
        uint32_t w3 = __byte_perm(l6, l7, 0x5410);
        asm volatile("st.shared.v4.b32 [%0], {%1,%2,%3,%4};"
                     :: "r"(bStage + bdoff), "r"(w0), "r"(w1), "r"(w2), "r"(w3)
                     : "memory");
    };

    // ---- ldmatrix offsets (16 warps: wm 0..7 x 64 rows, wn 0..1 x 32 cols) --
    const int wm = wid >> 1;
    const int wn = wid & 1;
    const int lr = lane & 7;
    const int lj = lane >> 3;
    uint32_t aOff[4][4], bOff[4][2];
#pragma unroll
    for (int ks = 0; ks < 4; ks++) {
#pragma unroll
        for (int mf = 0; mf < 4; mf++) {
            int row = wm * 64 + mf * 16 + lr + (lj & 1) * 8;
            int c16 = 2 * ks + (lj >> 1);
            aOff[ks][mf] = (uint32_t)(row * 128 + ((c16 ^ lr) << 4));
        }
#pragma unroll
        for (int nh = 0; nh < 2; nh++) {
            int nrow = wn * 32 + nh * 16 + lr + (lj >> 1) * 8;
            int c16  = 2 * ks + (lj & 1);
            bOff[ks][nh] = (uint32_t)(nrow * 128 + ((c16 ^ lr) << 4));
        }
    }

    float acc[4][4][4];
#pragma unroll
    for (int a = 0; a < 4; a++)
#pragma unroll
        for (int b = 0; b < 4; b++)
#pragma unroll
            for (int q = 0; q < 4; q++) acc[a][b][q] = 0.0f;

    // ---- prologue ----
    bLDG(0); bSTS(sB0);
    bLDG(1); bSTS(sB0 + BSZ);
    fillA(0, sA0);
    fillA(1, sA0 + ASZ);

    // ---- main loop ----
    int s = 0;
    for (int i = 0; i < NCH; i++) {
        const int t = (s + 2 >= 3) ? s - 1 : s + 2;   // (i+2)%3
        if (i < NCH - 1) asm volatile("cp.async.wait_group 1;" ::: "memory");
        else             asm volatile("cp.async.wait_group 0;" ::: "memory");
        __syncthreads();

        const bool refill = (i + 2 < NCH);
        if (refill) {
            bLDG(i + 2);
            fillA(i + 2, sA0 + t * ASZ);
        }

        uint32_t aBase = sA0 + s * ASZ;
        uint32_t bBase = sB0 + s * BSZ;
#pragma unroll
        for (int ks = 0; ks < 4; ks++) {
            uint32_t a_frag[4][4];
            uint32_t b_frag[4][2];
#pragma unroll
            for (int mf = 0; mf < 4; mf++)
                ldsm_x4(a_frag[mf], aBase + aOff[ks][mf]);
#pragma unroll
            for (int nh = 0; nh < 2; nh++) {
                uint32_t r[4];
                ldsm_x4(r, bBase + bOff[ks][nh]);
                b_frag[2 * nh][0]     = r[0];
                b_frag[2 * nh][1]     = r[1];
                b_frag[2 * nh + 1][0] = r[2];
                b_frag[2 * nh + 1][1] = r[3];
            }
#pragma unroll
            for (int mf = 0; mf < 4; mf++)
#pragma unroll
                for (int nf = 0; nf < 4; nf++)
                    mma16816(acc[mf][nf], a_frag[mf], b_frag[nf]);
        }

        if (refill) bSTS(sB0 + t * BSZ);

        if (++s == 3) s = 0;
    }

    // ---- epilogue: fp16 half2 stores into the partial plane ----
    __half* plane = g_part + (size_t)kq * PLANE;
    const int lq = lane >> 2;
    const int lp = lane & 3;
#pragma unroll
    for (int mf = 0; mf < 4; mf++) {
        int grow = wm * 64 + mf * 16 + lq;
#pragma unroll
        for (int nf = 0; nf < 4; nf++) {
            int gcol = n0 + wn * 32 + nf * 8 + 2 * lp;
            __half* p = plane + (size_t)grow * OUT_ + gcol;
            __half2 h0 = __floats2half2_rn(acc[mf][nf][0], acc[mf][nf][1]);
            __half2 h1 = __floats2half2_rn(acc[mf][nf][2], acc[mf][nf][3]);
            *reinterpret_cast<__half2*>(p)            = h0;
            *reinterpret_cast<__half2*>(p + 8 * OUT_) = h1;
        }
    }
}

// ---------------- reduce kernel: out = (sum(partials) + bias) * scale --------
__global__ void reduce_kernel(const float* __restrict__ bias,
                              const float* __restrict__ scale,
                              float* __restrict__ out) {
    const int n8 = (int)(PLANE / 8);
    int stride = gridDim.x * blockDim.x;
    for (int i = blockIdx.x * blockDim.x + threadIdx.x; i < n8; i += stride) {
        size_t e = (size_t)i * 8;
        int col = (int)(e % OUT_);          // OUT_ % 8 == 0, never crosses a row
        uint4 q0 = __ldg(reinterpret_cast<const uint4*>(g_part + e));
        uint4 q1 = __ldg(reinterpret_cast<const uint4*>(g_part + PLANE + e));
        uint4 q2 = __ldg(reinterpret_cast<const uint4*>(g_part + 2 * PLANE + e));
        uint4 q3 = __ldg(reinterpret_cast<const uint4*>(g_part + 3 * PLANE + e));
        float4 b0 = __ldg(reinterpret_cast<const float4*>(bias + col));
        float4 b1 = __ldg(reinterpret_cast<const float4*>(bias + col + 4));
        float4 c0 = __ldg(reinterpret_cast<const float4*>(scale + col));
        float4 c1 = __ldg(reinterpret_cast<const float4*>(scale + col + 4));
        float r[8];
#pragma unroll
        for (int w = 0; w < 4; w++) {
            uint32_t u0 = (&q0.x)[w], u1 = (&q1.x)[w], u2 = (&q2.x)[w], u3 = (&q3.x)[w];
            float2 f0 = __half22float2(*reinterpret_cast<__half2*>(&u0));
            float2 f1 = __half22float2(*reinterpret_cast<__half2*>(&u1));
            float2 f2 = __half22float2(*reinterpret_cast<__half2*>(&u2));
            float2 f3 = __half22float2(*reinterpret_cast<__half2*>(&u3));
            r[2 * w]     = f0.x + f1.x + f2.x + f3.x;
            r[2 * w + 1] = f0.y + f1.y + f2.y + f3.y;
        }
        float4 o0, o1;
        o0.x = (r[0] + b0.x) * c0.x;
        o0.y = (r[1] + b0.y) * c0.y;
        o0.z = (r[2] + b0.z) * c0.z;
        o0.w = (r[3] + b0.w) * c0.w;
        o1.x = (r[4] + b1.x) * c1.x;
        o1.y = (r[5] + b1.y) * c1.y;
        o1.z = (r[6] + b1.z) * c1.z;
        o1.w = (r[7] + b1.w) * c1.w;
        reinterpret_cast<float4*>(out + e)[0] = o0;
        reinterpret_cast<float4*>(out + e)[1] = o1;
    }
}

// ---------------- launch -----------------------------------------------------
extern "C" void kernel_launch(void* const* d_in, const int* in_sizes, int n_in,
                              void* d_out, int out_size) {
    const float* x      = (const float*)d_in[0];
    const int*   stored = (const int*)d_in[1];
    const int*   sign   = (const int*)d_in[2];
    const float* lmin   = (const float*)d_in[3];
    const float* lmax   = (const float*)d_in[4];
    const float* scale  = (const float*)d_in[5];
    const float* bias   = (const float*)d_in[6];
    float* out = (float*)d_out;

    cudaFuncSetAttribute(fused_kernel, cudaFuncAttributeMaxDynamicSharedMemorySize,
                         (int)SMEM_REQ);

    xconv_kernel<<<512, 256>>>(x);
    fused_kernel<<<NTILES * KSPLIT, 512, SMEM_REQ>>>(stored, sign, lmin, lmax);
    reduce_kernel<<<2048, 256>>>(bias, scale, out);
}

// round 14
// speedup vs baseline: 1.5775x; 1.0689x over previous
#include <cuda_runtime.h>
#include <cuda_fp16.h>
#include <cstdint>
#include <cstddef>

#define B_   512
#define IN_  4096
#define OUT_ 11008

#define MT      512
#define NT      64
#define NTILES  172          // OUT / NT
#define KSPLIT  4
#define KPART   1024         // IN / KSPLIT
#define BK      64
#define NCH     16           // KPART / BK
#define PLANE   ((size_t)B_ * OUT_)

// static device scratch (no runtime allocation)
__device__ __align__(1024) __half g_x[(size_t)B_ * IN_];
__device__ __align__(1024) __half g_part[KSPLIT * PLANE];   // 45 MB fp16 partials

// ---------------- helpers ----------------------------------------------------
__device__ __forceinline__ uint32_t smem_u32(const void* p) {
    uint32_t a;
    asm("{ .reg .u64 t; cvta.to.shared.u64 t, %1; cvt.u32.u64 %0, t; }"
        : "=r"(a) : "l"(p));
    return a;
}
#define CP16(dst, src) \
    asm volatile("cp.async.cg.shared.global [%0], [%1], 16;" :: "r"(dst), "l"(src))
#define CP_COMMIT() asm volatile("cp.async.commit_group;" ::: "memory")

__device__ __forceinline__ void ldsm_x4(uint32_t* r, uint32_t addr) {
    asm volatile("ldmatrix.sync.aligned.m8n8.x4.shared.b16 {%0,%1,%2,%3}, [%4];"
                 : "=r"(r[0]), "=r"(r[1]), "=r"(r[2]), "=r"(r[3]) : "r"(addr));
}
__device__ __forceinline__ void mma16816(float* c, const uint32_t* a, const uint32_t* b) {
    asm volatile(
        "mma.sync.aligned.m16n8k16.row.col.f32.f16.f16.f32 "
        "{%0,%1,%2,%3}, {%4,%5,%6,%7}, {%8,%9}, {%0,%1,%2,%3};\n"
        : "+f"(c[0]), "+f"(c[1]), "+f"(c[2]), "+f"(c[3])
        : "r"(a[0]), "r"(a[1]), "r"(a[2]), "r"(a[3]), "r"(b[0]), "r"(b[1]));
}

// ---------------- kernel 1: x fp32 -> fp16 (1 float4 per thread) -------------
__global__ void xconv_kernel(const float* __restrict__ x) {
    int i = blockIdx.x * blockDim.x + threadIdx.x;      // grid covers n4 exactly
    float4 v = reinterpret_cast<const float4*>(x)[i];
    __half2 lo = __floats2half2_rn(v.x, v.y);
    __half2 hi = __floats2half2_rn(v.z, v.w);
    uint2 o;
    o.x = *reinterpret_cast<uint32_t*>(&lo);
    o.y = *reinterpret_cast<uint32_t*>(&hi);
    reinterpret_cast<uint2*>(g_x)[i] = o;
}

// ---------------- fused dequant + GEMM kernel --------------------------------
// Tile: M=512, N=64, K=1024. Grid = 172 x 4. 3-stage XOR-swizzled smem pipe.
// Swizzle: 128B rows, 16B chunk c16' = c16 ^ (row & 7).
static constexpr uint32_t ASZ = MT * 128;            // 65536 per stage
static constexpr uint32_t BSZ = NT * 128;            // 8192 per stage
static constexpr uint32_t SMEM_REQ = 3 * ASZ + 3 * BSZ + 2048;  // 223232

__global__ void __launch_bounds__(512, 1)
fused_kernel(const int* __restrict__ stored, const int* __restrict__ sign,
             const float* __restrict__ lmin_p, const float* __restrict__ lmax_p) {
    extern __shared__ char smem[];
    const uint32_t sA0 = smem_u32(smem);
    const uint32_t sB0 = sA0 + 3 * ASZ;
    unsigned* lut = reinterpret_cast<unsigned*>(smem + 3 * ASZ + 3 * BSZ);

    const int tid  = threadIdx.x;
    const int wid  = tid >> 5;
    const int lane = tid & 31;
    const int ntile = blockIdx.x % NTILES;
    const int kq    = blockIdx.x / NTILES;
    const int n0    = ntile * NT;
    const int k0    = kq * KPART;

    // ---- build LUT ----
    {
        float lmin = __ldg(lmin_p);
        float lmax = __ldg(lmax_p);
        if (tid < 511) {
            int s = tid - 255;
            int mag = s < 0 ? -s : s;
            float w = 0.0f;
            if (s != 0) {
                float nrm = (255.0f - (float)mag) * (1.0f / 254.0f);
                w = expf(lmin + nrm * (lmax - lmin));
                if (s < 0) w = -w;
            }
            unsigned hb = (unsigned)__half_as_ushort(__float2half_rn(w));
            lut[tid] = hb | (hb << 16);
        }
    }
    __syncthreads();

    // ---- A fill geometry: 8 x 16B chunks per thread, swizzled ----
    int arow[8];
    uint32_t adoff[8];
    int asrc[8];
#pragma unroll
    for (int j = 0; j < 8; j++) {
        int idx = j * 512 + tid;          // 0..4095
        int row = idx >> 3;
        int c16 = idx & 7;
        arow[j] = row;
        asrc[j] = c16 * 8;
        adoff[j] = (uint32_t)(row * 128 + ((c16 ^ (row & 7)) << 4));
    }
    auto fillA = [&](int chunk, uint32_t aStage) {
        const __half* base = g_x + k0 + chunk * BK;
#pragma unroll
        for (int j = 0; j < 8; j++)
            CP16(aStage + adoff[j], base + (size_t)arow[j] * IN_ + asrc[j]);
        CP_COMMIT();
    };

    // ---- B dequant: 8 elems (one 16B chunk) per thread ----
    const int drow = tid >> 3;
    const int dc16 = tid & 7;
    const int* stp = stored + (size_t)(n0 + drow) * IN_ + k0 + dc16 * 8;
    const int* sgp = sign   + (size_t)(n0 + drow) * IN_ + k0 + dc16 * 8;
    const uint32_t bdoff = (uint32_t)(drow * 128 + ((dc16 ^ (drow & 7)) << 4));

    int4 st0, st1, sg0, sg1;
    auto bLDG = [&](int chunk) {
        const int4* a = reinterpret_cast<const int4*>(stp + chunk * BK);
        const int4* b = reinterpret_cast<const int4*>(sgp + chunk * BK);
        st0 = a[0]; st1 = a[1];
        sg0 = b[0]; sg1 = b[1];
    };
    auto bSTS = [&](uint32_t bStage) {
        unsigned l0 = lut[sg0.x * st0.x + 255];
        unsigned l1 = lut[sg0.y * st0.y + 255];
        unsigned l2 = lut[sg0.z * st0.z + 255];
        unsigned l3 = lut[sg0.w * st0.w + 255];
        unsigned l4 = lut[sg1.x * st1.x + 255];
        unsigned l5 = lut[sg1.y * st1.y + 255];
        unsigned l6 = lut[sg1.z * st1.z + 255];
        unsigned l7 = lut[sg1.w * st1.w + 255];
        uint32_t w0 = __byte_perm(l0, l1, 0x5410);
        uint32_t w1 = __byte_perm(l2, l3, 0x5410);
        uint32_t w2 = __byte_perm(l4, l5, 0x5410);
        uint32_t w3 = __byte_perm(l6, l7, 0x5410);
        asm volatile("st.shared.v4.b32 [%0], {%1,%2,%3,%4};"
                     :: "r"(bStage + bdoff), "r"(w0), "r"(w1), "r"(w2), "r"(w3)
                     : "memory");
    };

    // ---- ldmatrix offsets (16 warps: wm 0..7 x 64 rows, wn 0..1 x 32 cols) --
    const int wm = wid >> 1;
    const int wn = wid & 1;
    const int lr = lane & 7;
    const int lj = lane >> 3;
    uint32_t aOff[4][4], bOff[4][2];
#pragma unroll
    for (int ks = 0; ks < 4; ks++) {
#pragma unroll
        for (int mf = 0; mf < 4; mf++) {
            int row = wm * 64 + mf * 16 + lr + (lj & 1) * 8;
            int c16 = 2 * ks + (lj >> 1);
            aOff[ks][mf] = (uint32_t)(row * 128 + ((c16 ^ lr) << 4));
        }
#pragma unroll
        for (int nh = 0; nh < 2; nh++) {
            int nrow = wn * 32 + nh * 16 + lr + (lj >> 1) * 8;
            int c16  = 2 * ks + (lj & 1);
            bOff[ks][nh] = (uint32_t)(nrow * 128 + ((c16 ^ lr) << 4));
        }
    }

    float acc[4][4][4];
#pragma unroll
    for (int a = 0; a < 4; a++)
#pragma unroll
        for (int b = 0; b < 4; b++)
#pragma unroll
            for (int q = 0; q < 4; q++) acc[a][b][q] = 0.0f;

    // ---- prologue ----
    bLDG(0); bSTS(sB0);
    bLDG(1); bSTS(sB0 + BSZ);
    fillA(0, sA0);
    fillA(1, sA0 + ASZ);

    // ---- main loop ----
    int s = 0;
    for (int i = 0; i < NCH; i++) {
        const int t = (s + 2 >= 3) ? s - 1 : s + 2;   // (i+2)%3
        const bool refill = (i + 2 < NCH);

        // B LDG for chunk i+2: regs are dead, no smem touched -> issue BEFORE
        // the barrier so its latency overlaps the wait.
        if (refill) bLDG(i + 2);

        if (i < NCH - 1) asm volatile("cp.async.wait_group 1;" ::: "memory");
        else             asm volatile("cp.async.wait_group 0;" ::: "memory");
        __syncthreads();

        if (refill) fillA(i + 2, sA0 + t * ASZ);

        uint32_t aBase = sA0 + s * ASZ;
        uint32_t bBase = sB0 + s * BSZ;
#pragma unroll
        for (int ks = 0; ks < 4; ks++) {
            uint32_t a_frag[4][4];
            uint32_t b_frag[4][2];
#pragma unroll
            for (int mf = 0; mf < 4; mf++)
                ldsm_x4(a_frag[mf], aBase + aOff[ks][mf]);
#pragma unroll
            for (int nh = 0; nh < 2; nh++) {
                uint32_t r[4];
                ldsm_x4(r, bBase + bOff[ks][nh]);
                b_frag[2 * nh][0]     = r[0];
                b_frag[2 * nh][1]     = r[1];
                b_frag[2 * nh + 1][0] = r[2];
                b_frag[2 * nh + 1][1] = r[3];
            }
#pragma unroll
            for (int mf = 0; mf < 4; mf++)
#pragma unroll
                for (int nf = 0; nf < 4; nf++)
                    mma16816(acc[mf][nf], a_frag[mf], b_frag[nf]);
        }

        if (refill) bSTS(sB0 + t * BSZ);

        if (++s == 3) s = 0;
    }

    // ---- epilogue: fp16 half2 stores into the partial plane ----
    __half* plane = g_part + (size_t)kq * PLANE;
    const int lq = lane >> 2;
    const int lp = lane & 3;
#pragma unroll
    for (int mf = 0; mf < 4; mf++) {
        int grow = wm * 64 + mf * 16 + lq;
#pragma unroll
        for (int nf = 0; nf < 4; nf++) {
            int gcol = n0 + wn * 32 + nf * 8 + 2 * lp;
            __half* p = plane + (size_t)grow * OUT_ + gcol;
            __half2 h0 = __floats2half2_rn(acc[mf][nf][0], acc[mf][nf][1]);
            __half2 h1 = __floats2half2_rn(acc[mf][nf][2], acc[mf][nf][3]);
            *reinterpret_cast<__half2*>(p)            = h0;
            *reinterpret_cast<__half2*>(p + 8 * OUT_) = h1;
        }
    }
}

// ---------------- reduce kernel: out = (sum(partials) + bias) * scale --------
// grid x block covers PLANE/8 exactly: 1 item (8 cols) per thread, no loop.
__global__ void reduce_kernel(const float* __restrict__ bias,
                              const float* __restrict__ scale,
                              float* __restrict__ out) {
    int i = blockIdx.x * blockDim.x + threadIdx.x;
    size_t e = (size_t)i * 8;
    int col = (int)(e % OUT_);              // OUT_ % 8 == 0, never crosses a row
    uint4 q0 = __ldg(reinterpret_cast<const uint4*>(g_part + e));
    uint4 q1 = __ldg(reinterpret_cast<const uint4*>(g_part + PLANE + e));
    uint4 q2 = __ldg(reinterpret_cast<const uint4*>(g_part + 2 * PLANE + e));
    uint4 q3 = __ldg(reinterpret_cast<const uint4*>(g_part + 3 * PLANE + e));
    float4 b0 = __ldg(reinterpret_cast<const float4*>(bias + col));
    float4 b1 = __ldg(reinterpret_cast<const float4*>(bias + col + 4));
    float4 c0 = __ldg(reinterpret_cast<const float4*>(scale + col));
    float4 c1 = __ldg(reinterpret_cast<const float4*>(scale + col + 4));
    float r[8];
#pragma unroll
    for (int w = 0; w < 4; w++) {
        uint32_t u0 = (&q0.x)[w], u1 = (&q1.x)[w], u2 = (&q2.x)[w], u3 = (&q3.x)[w];
        float2 f0 = __half22float2(*reinterpret_cast<__half2*>(&u0));
        float2 f1 = __half22float2(*reinterpret_cast<__half2*>(&u1));
        float2 f2 = __half22float2(*reinterpret_cast<__half2*>(&u2));
        float2 f3 = __half22float2(*reinterpret_cast<__half2*>(&u3));
        r[2 * w]     = f0.x + f1.x + f2.x + f3.x;
        r[2 * w + 1] = f0.y + f1.y + f2.y + f3.y;
    }
    float4 o0, o1;
    o0.x = (r[0] + b0.x) * c0.x;
    o0.y = (r[1] + b0.y) * c0.y;
    o0.z = (r[2] + b0.z) * c0.z;
    o0.w = (r[3] + b0.w) * c0.w;
    o1.x = (r[4] + b1.x) * c1.x;
    o1.y = (r[5] + b1.y) * c1.y;
    o1.z = (r[6] + b1.z) * c1.z;
    o1.w = (r[7] + b1.w) * c1.w;
    reinterpret_cast<float4*>(out + e)[0] = o0;
    reinterpret_cast<float4*>(out + e)[1] = o1;
}

// ---------------- launch -----------------------------------------------------
extern "C" void kernel_launch(void* const* d_in, const int* in_sizes, int n_in,
                              void* d_out, int out_size) {
    const float* x      = (const float*)d_in[0];
    const int*   stored = (const int*)d_in[1];
    const int*   sign   = (const int*)d_in[2];
    const float* lmin   = (const float*)d_in[3];
    const float* lmax   = (const float*)d_in[4];
    const float* scale  = (const float*)d_in[5];
    const float* bias   = (const float*)d_in[6];
    float* out = (float*)d_out;

    cudaFuncSetAttribute(fused_kernel, cudaFuncAttributeMaxDynamicSharedMemorySize,
                         (int)SMEM_REQ);

    xconv_kernel<<<2048, 256>>>(x);                       // 2048*256 = (B*IN)/4
    fused_kernel<<<NTILES * KSPLIT, 512, SMEM_REQ>>>(stored, sign, lmin, lmax);
    reduce_kernel<<<2752, 256>>>(bias, scale, out);       // 2752*256 = PLANE/8
}

// round 15
// speedup vs baseline: 1.7536x; 1.1116x over previous
#include <cuda_runtime.h>
#include <cuda_fp16.h>
#include <cstdint>
#include <cstddef>

#define B_   512
#define IN_  4096
#define OUT_ 11008

#define MT      512
#define NT      64
#define NTILES  172          // OUT / NT
#define BK      64
#define PLANE   ((size_t)B_ * OUT_)

// Mixed split: ntiles [76,172) -> 3 CTAs (22/21/21 chunks), bids [0,288)
//              ntiles [0,76)   -> 4 CTAs (16 chunks each), bids [288,592)
#define GRID_FUSED 592
#define COL_SPLIT3 4864      // 76 * 64: cols >= this use 3 partial planes

// static device scratch (no runtime allocation)
__device__ __align__(1024) __half g_x[(size_t)B_ * IN_];
__device__ __align__(1024) __half g_part[4 * PLANE];   // 45 MB fp16 partials

// ---------------- helpers ----------------------------------------------------
__device__ __forceinline__ uint32_t smem_u32(const void* p) {
    uint32_t a;
    asm("{ .reg .u64 t; cvta.to.shared.u64 t, %1; cvt.u32.u64 %0, t; }"
        : "=r"(a) : "l"(p));
    return a;
}
#define CP16(dst, src) \
    asm volatile("cp.async.cg.shared.global [%0], [%1], 16;" :: "r"(dst), "l"(src))
#define CP_COMMIT() asm volatile("cp.async.commit_group;" ::: "memory")

__device__ __forceinline__ void ldsm_x4(uint32_t* r, uint32_t addr) {
    asm volatile("ldmatrix.sync.aligned.m8n8.x4.shared.b16 {%0,%1,%2,%3}, [%4];"
                 : "=r"(r[0]), "=r"(r[1]), "=r"(r[2]), "=r"(r[3]) : "r"(addr));
}
__device__ __forceinline__ void mma16816(float* c, const uint32_t* a, const uint32_t* b) {
    asm volatile(
        "mma.sync.aligned.m16n8k16.row.col.f32.f16.f16.f32 "
        "{%0,%1,%2,%3}, {%4,%5,%6,%7}, {%8,%9}, {%0,%1,%2,%3};\n"
        : "+f"(c[0]), "+f"(c[1]), "+f"(c[2]), "+f"(c[3])
        : "r"(a[0]), "r"(a[1]), "r"(a[2]), "r"(a[3]), "r"(b[0]), "r"(b[1]));
}

// ---------------- kernel 1: x fp32 -> fp16 (1 float4 per thread) -------------
__global__ void xconv_kernel(const float* __restrict__ x) {
    int i = blockIdx.x * blockDim.x + threadIdx.x;      // grid covers n4 exactly
    float4 v = reinterpret_cast<const float4*>(x)[i];
    __half2 lo = __floats2half2_rn(v.x, v.y);
    __half2 hi = __floats2half2_rn(v.z, v.w);
    uint2 o;
    o.x = *reinterpret_cast<uint32_t*>(&lo);
    o.y = *reinterpret_cast<uint32_t*>(&hi);
    reinterpret_cast<uint2*>(g_x)[i] = o;
}

// ---------------- fused dequant + GEMM kernel --------------------------------
// Tile: M=512, N=64, variable K part. 3-stage XOR-swizzled smem pipe.
// Swizzle: 128B rows, 16B chunk c16' = c16 ^ (row & 7).
static constexpr uint32_t ASZ = MT * 128;            // 65536 per stage
static constexpr uint32_t BSZ = NT * 128;            // 8192 per stage
static constexpr uint32_t SMEM_REQ = 3 * ASZ + 3 * BSZ + 2048;  // 223232

__global__ void __launch_bounds__(512, 1)
fused_kernel(const int* __restrict__ stored, const int* __restrict__ sign,
             const float* __restrict__ lmin_p, const float* __restrict__ lmax_p) {
    extern __shared__ char smem[];
    const uint32_t sA0 = smem_u32(smem);
    const uint32_t sB0 = sA0 + 3 * ASZ;
    unsigned* lut = reinterpret_cast<unsigned*>(smem + 3 * ASZ + 3 * BSZ);

    const int tid  = threadIdx.x;
    const int wid  = tid >> 5;
    const int lane = tid & 31;

    // ---- bid -> (ntile, kq, chunk base c0, chunk count nch) ----
    int ntile, kq, c0, nch;
    if (blockIdx.x < 288) {                 // long CTAs first (LPT dispatch)
        int u = blockIdx.x;
        ntile = 76 + u / 3;
        kq = u - 3 * (u / 3);
        c0  = (kq == 0) ? 0 : (kq == 1 ? 22 : 43);
        nch = (kq == 0) ? 22 : 21;
    } else {
        int v = blockIdx.x - 288;
        ntile = v >> 2;
        kq = v & 3;
        c0  = kq * 16;
        nch = 16;
    }
    const int n0 = ntile * NT;
    const int k0 = c0 * BK;

    // ---- build LUT ----
    {
        float lmin = __ldg(lmin_p);
        float lmax = __ldg(lmax_p);
        if (tid < 511) {
            int s = tid - 255;
            int mag = s < 0 ? -s : s;
            float w = 0.0f;
            if (s != 0) {
                float nrm = (255.0f - (float)mag) * (1.0f / 254.0f);
                w = expf(lmin + nrm * (lmax - lmin));
                if (s < 0) w = -w;
            }
            unsigned hb = (unsigned)__half_as_ushort(__float2half_rn(w));
            lut[tid] = hb | (hb << 16);
        }
    }
    __syncthreads();

    // ---- A fill geometry: 8 x 16B chunks per thread, swizzled ----
    int arow[8];
    uint32_t adoff[8];
    int asrc[8];
#pragma unroll
    for (int j = 0; j < 8; j++) {
        int idx = j * 512 + tid;          // 0..4095
        int row = idx >> 3;
        int c16 = idx & 7;
        arow[j] = row;
        asrc[j] = c16 * 8;
        adoff[j] = (uint32_t)(row * 128 + ((c16 ^ (row & 7)) << 4));
    }
    auto fillA = [&](int chunk, uint32_t aStage) {
        const __half* base = g_x + k0 + chunk * BK;
#pragma unroll
        for (int j = 0; j < 8; j++)
            CP16(aStage + adoff[j], base + (size_t)arow[j] * IN_ + asrc[j]);
        CP_COMMIT();
    };

    // ---- B dequant: 8 elems (one 16B chunk) per thread ----
    const int drow = tid >> 3;
    const int dc16 = tid & 7;
    const int* stp = stored + (size_t)(n0 + drow) * IN_ + k0 + dc16 * 8;
    const int* sgp = sign   + (size_t)(n0 + drow) * IN_ + k0 + dc16 * 8;
    const uint32_t bdoff = (uint32_t)(drow * 128 + ((dc16 ^ (drow & 7)) << 4));

    int4 st0, st1, sg0, sg1;
    auto bLDG = [&](int chunk) {
        const int4* a = reinterpret_cast<const int4*>(stp + chunk * BK);
        const int4* b = reinterpret_cast<const int4*>(sgp + chunk * BK);
        st0 = a[0]; st1 = a[1];
        sg0 = b[0]; sg1 = b[1];
    };
    auto bSTS = [&](uint32_t bStage) {
        unsigned l0 = lut[sg0.x * st0.x + 255];
        unsigned l1 = lut[sg0.y * st0.y + 255];
        unsigned l2 = lut[sg0.z * st0.z + 255];
        unsigned l3 = lut[sg0.w * st0.w + 255];
        unsigned l4 = lut[sg1.x * st1.x + 255];
        unsigned l5 = lut[sg1.y * st1.y + 255];
        unsigned l6 = lut[sg1.z * st1.z + 255];
        unsigned l7 = lut[sg1.w * st1.w + 255];
        uint32_t w0 = __byte_perm(l0, l1, 0x5410);
        uint32_t w1 = __byte_perm(l2, l3, 0x5410);
        uint32_t w2 = __byte_perm(l4, l5, 0x5410);
        uint32_t w3 = __byte_perm(l6, l7, 0x5410);
        asm volatile("st.shared.v4.b32 [%0], {%1,%2,%3,%4};"
                     :: "r"(bStage + bdoff), "r"(w0), "r"(w1), "r"(w2), "r"(w3)
                     : "memory");
    };

    // ---- ldmatrix offsets (16 warps: wm 0..7 x 64 rows, wn 0..1 x 32 cols) --
    const int wm = wid >> 1;
    const int wn = wid & 1;
    const int lr = lane & 7;
    const int lj = lane >> 3;
    uint32_t aOff[4][4], bOff[4][2];
#pragma unroll
    for (int ks = 0; ks < 4; ks++) {
#pragma unroll
        for (int mf = 0; mf < 4; mf++) {
            int row = wm * 64 + mf * 16 + lr + (lj & 1) * 8;
            int c16 = 2 * ks + (lj >> 1);
            aOff[ks][mf] = (uint32_t)(row * 128 + ((c16 ^ lr) << 4));
        }
#pragma unroll
        for (int nh = 0; nh < 2; nh++) {
            int nrow = wn * 32 + nh * 16 + lr + (lj >> 1) * 8;
            int c16  = 2 * ks + (lj & 1);
            bOff[ks][nh] = (uint32_t)(nrow * 128 + ((c16 ^ lr) << 4));
        }
    }

    float acc[4][4][4];
#pragma unroll
    for (int a = 0; a < 4; a++)
#pragma unroll
        for (int b = 0; b < 4; b++)
#pragma unroll
            for (int q = 0; q < 4; q++) acc[a][b][q] = 0.0f;

    // ---- prologue ----
    bLDG(0); bSTS(sB0);
    bLDG(1); bSTS(sB0 + BSZ);
    fillA(0, sA0);
    fillA(1, sA0 + ASZ);

    // ---- main loop (variable nch) ----
    int s = 0;
    for (int i = 0; i < nch; i++) {
        const int t = (s + 2 >= 3) ? s - 1 : s + 2;   // (i+2)%3
        const bool refill = (i + 2 < nch);

        // B LDG for chunk i+2: regs are dead, no smem touched -> issue BEFORE
        // the barrier so its latency overlaps the wait.
        if (refill) bLDG(i + 2);

        if (i < nch - 1) asm volatile("cp.async.wait_group 1;" ::: "memory");
        else             asm volatile("cp.async.wait_group 0;" ::: "memory");
        __syncthreads();

        if (refill) fillA(i + 2, sA0 + t * ASZ);

        uint32_t aBase = sA0 + s * ASZ;
        uint32_t bBase = sB0 + s * BSZ;
#pragma unroll
        for (int ks = 0; ks < 4; ks++) {
            uint32_t a_frag[4][4];
            uint32_t b_frag[4][2];
#pragma unroll
            for (int mf = 0; mf < 4; mf++)
                ldsm_x4(a_frag[mf], aBase + aOff[ks][mf]);
#pragma unroll
            for (int nh = 0; nh < 2; nh++) {
                uint32_t r[4];
                ldsm_x4(r, bBase + bOff[ks][nh]);
                b_frag[2 * nh][0]     = r[0];
                b_frag[2 * nh][1]     = r[1];
                b_frag[2 * nh + 1][0] = r[2];
                b_frag[2 * nh + 1][1] = r[3];
            }
#pragma unroll
            for (int mf = 0; mf < 4; mf++)
#pragma unroll
                for (int nf = 0; nf < 4; nf++)
                    mma16816(acc[mf][nf], a_frag[mf], b_frag[nf]);
        }

        if (refill) bSTS(sB0 + t * BSZ);

        if (++s == 3) s = 0;
    }

    // ---- epilogue: fp16 half2 stores into the partial plane ----
    __half* plane = g_part + (size_t)kq * PLANE;
    const int lq = lane >> 2;
    const int lp = lane & 3;
#pragma unroll
    for (int mf = 0; mf < 4; mf++) {
        int grow = wm * 64 + mf * 16 + lq;
#pragma unroll
        for (int nf = 0; nf < 4; nf++) {
            int gcol = n0 + wn * 32 + nf * 8 + 2 * lp;
            __half* p = plane + (size_t)grow * OUT_ + gcol;
            __half2 h0 = __floats2half2_rn(acc[mf][nf][0], acc[mf][nf][1]);
            __half2 h1 = __floats2half2_rn(acc[mf][nf][2], acc[mf][nf][3]);
            *reinterpret_cast<__half2*>(p)            = h0;
            *reinterpret_cast<__half2*>(p + 8 * OUT_) = h1;
        }
    }
}

// ---------------- reduce kernel: out = (sum(partials) + bias) * scale --------
// grid x block covers PLANE/8 exactly: 1 item (8 cols) per thread, no loop.
// Cols < COL_SPLIT3 have 4 partial planes; cols >= COL_SPLIT3 have 3.
__global__ void reduce_kernel(const float* __restrict__ bias,
                              const float* __restrict__ scale,
                              float* __restrict__ out) {
    int i = blockIdx.x * blockDim.x + threadIdx.x;
    size_t e = (size_t)i * 8;
    int col = (int)(e % OUT_);              // OUT_ % 8 == 0, never crosses a row
    uint4 q0 = __ldg(reinterpret_cast<const uint4*>(g_part + e));
    uint4 q1 = __ldg(reinterpret_cast<const uint4*>(g_part + PLANE + e));
    uint4 q2 = __ldg(reinterpret_cast<const uint4*>(g_part + 2 * PLANE + e));
    float4 b0 = __ldg(reinterpret_cast<const float4*>(bias + col));
    float4 b1 = __ldg(reinterpret_cast<const float4*>(bias + col + 4));
    float4 c0 = __ldg(reinterpret_cast<const float4*>(scale + col));
    float4 c1 = __ldg(reinterpret_cast<const float4*>(scale + col + 4));
    float r[8];
#pragma unroll
    for (int w = 0; w < 4; w++) {
        uint32_t u0 = (&q0.x)[w], u1 = (&q1.x)[w], u2 = (&q2.x)[w];
        float2 f0 = __half22float2(*reinterpret_cast<__half2*>(&u0));
        float2 f1 = __half22float2(*reinterpret_cast<__half2*>(&u1));
        float2 f2 = __half22float2(*reinterpret_cast<__half2*>(&u2));
        r[2 * w]     = f0.x + f1.x + f2.x;
        r[2 * w + 1] = f0.y + f1.y + f2.y;
    }
    if (col < COL_SPLIT3) {                 // 4-split tiles: add plane 3
        uint4 q3 = __ldg(reinterpret_cast<const uint4*>(g_part + 3 * PLANE + e));
#pragma unroll
        for (int w = 0; w < 4; w++) {
            uint32_t u3 = (&q3.x)[w];
            float2 f3 = __half22float2(*reinterpret_cast<__half2*>(&u3));
            r[2 * w]     += f3.x;
            r[2 * w + 1] += f3.y;
        }
    }
    float4 o0, o1;
    o0.x = (r[0] + b0.x) * c0.x;
    o0.y = (r[1] + b0.y) * c0.y;
    o0.z = (r[2] + b0.z) * c0.z;
    o0.w = (r[3] + b0.w) * c0.w;
    o1.x = (r[4] + b1.x) * c1.x;
    o1.y = (r[5] + b1.y) * c1.y;
    o1.z = (r[6] + b1.z) * c1.z;
    o1.w = (r[7] + b1.w) * c1.w;
    reinterpret_cast<float4*>(out + e)[0] = o0;
    reinterpret_cast<float4*>(out + e)[1] = o1;
}

// ---------------- launch -----------------------------------------------------
extern "C" void kernel_launch(void* const* d_in, const int* in_sizes, int n_in,
                              void* d_out, int out_size) {
    const float* x      = (const float*)d_in[0];
    const int*   stored = (const int*)d_in[1];
    const int*   sign   = (const int*)d_in[2];
    const float* lmin   = (const float*)d_in[3];
    const float* lmax   = (const float*)d_in[4];
    const float* scale  = (const float*)d_in[5];
    const float* bias   = (const float*)d_in[6];
    float* out = (float*)d_out;

    cudaFuncSetAttribute(fused_kernel, cudaFuncAttributeMaxDynamicSharedMemorySize,
                         (int)SMEM_REQ);

    xconv_kernel<<<2048, 256>>>(x);                       // 2048*256 = (B*IN)/4
    fused_kernel<<<GRID_FUSED, 512, SMEM_REQ>>>(stored, sign, lmin, lmax);
    reduce_kernel<<<2752, 256>>>(bias, scale, out);       // 2752*256 = PLANE/8
}

// round 16
// speedup vs baseline: 1.7707x; 1.0098x over previous
#include <cuda_runtime.h>
#include <cuda_fp16.h>
#include <cstdint>
#include <cstddef>

#define B_   512
#define IN_  4096
#define OUT_ 11008

#define MT      512
#define NT      64
#define NTILES  172          // OUT / NT
#define BK      64
#define PLANE   ((size_t)B_ * OUT_)

// Mixed split: ntiles [76,172) -> 3 CTAs (22/21/21 chunks), bids [0,288)
//              ntiles [0,76)   -> 4 CTAs (16 chunks each), bids [288,592)
#define GRID_FUSED 592
#define COL_SPLIT3 4864      // 76 * 64: cols >= this use 3 partial planes

// static device scratch (no runtime allocation)
__device__ __align__(1024) __half g_x[(size_t)B_ * IN_];
__device__ __align__(1024) __half g_part[4 * PLANE];   // 45 MB fp16 partials

// ---------------- helpers ----------------------------------------------------
__device__ __forceinline__ uint32_t smem_u32(const void* p) {
    uint32_t a;
    asm("{ .reg .u64 t; cvta.to.shared.u64 t, %1; cvt.u32.u64 %0, t; }"
        : "=r"(a) : "l"(p));
    return a;
}
#define GRIDDEP_WAIT() asm volatile("griddepcontrol.wait;" ::: "memory")
#define CP16(dst, src) \
    asm volatile("cp.async.cg.shared.global [%0], [%1], 16;" :: "r"(dst), "l"(src))
#define CP_COMMIT() asm volatile("cp.async.commit_group;" ::: "memory")

__device__ __forceinline__ void ldsm_x4(uint32_t* r, uint32_t addr) {
    asm volatile("ldmatrix.sync.aligned.m8n8.x4.shared.b16 {%0,%1,%2,%3}, [%4];"
                 : "=r"(r[0]), "=r"(r[1]), "=r"(r[2]), "=r"(r[3]) : "r"(addr));
}
__device__ __forceinline__ void mma16816(float* c, const uint32_t* a, const uint32_t* b) {
    asm volatile(
        "mma.sync.aligned.m16n8k16.row.col.f32.f16.f16.f32 "
        "{%0,%1,%2,%3}, {%4,%5,%6,%7}, {%8,%9}, {%0,%1,%2,%3};\n"
        : "+f"(c[0]), "+f"(c[1]), "+f"(c[2]), "+f"(c[3])
        : "r"(a[0]), "r"(a[1]), "r"(a[2]), "r"(a[3]), "r"(b[0]), "r"(b[1]));
}

// ---------------- kernel 1: x fp32 -> fp16 (2 float4 per thread, MLP=2) ------
__global__ void xconv_kernel(const float* __restrict__ x) {
    int i = blockIdx.x * blockDim.x + threadIdx.x;    // grid*2 covers n4 exactly
    float4 v0 = reinterpret_cast<const float4*>(x)[i];
    float4 v1 = reinterpret_cast<const float4*>(x)[i + 262144];
    __half2 a0 = __floats2half2_rn(v0.x, v0.y);
    __half2 a1 = __floats2half2_rn(v0.z, v0.w);
    __half2 b0 = __floats2half2_rn(v1.x, v1.y);
    __half2 b1 = __floats2half2_rn(v1.z, v1.w);
    uint2 o0, o1;
    o0.x = *reinterpret_cast<uint32_t*>(&a0);
    o0.y = *reinterpret_cast<uint32_t*>(&a1);
    o1.x = *reinterpret_cast<uint32_t*>(&b0);
    o1.y = *reinterpret_cast<uint32_t*>(&b1);
    reinterpret_cast<uint2*>(g_x)[i]          = o0;
    reinterpret_cast<uint2*>(g_x)[i + 262144] = o1;
}

// ---------------- fused dequant + GEMM kernel --------------------------------
// Tile: M=512, N=64, variable K part. 3-stage XOR-swizzled smem pipe.
// Swizzle: 128B rows, 16B chunk c16' = c16 ^ (row & 7).
static constexpr uint32_t ASZ = MT * 128;            // 65536 per stage
static constexpr uint32_t BSZ = NT * 128;            // 8192 per stage
static constexpr uint32_t SMEM_REQ = 3 * ASZ + 3 * BSZ + 2048;  // 223232

__global__ void __launch_bounds__(512, 1)
fused_kernel(const int* __restrict__ stored, const int* __restrict__ sign,
             const float* __restrict__ lmin_p, const float* __restrict__ lmax_p) {
    extern __shared__ char smem[];
    const uint32_t sA0 = smem_u32(smem);
    const uint32_t sB0 = sA0 + 3 * ASZ;
    unsigned* lut = reinterpret_cast<unsigned*>(smem + 3 * ASZ + 3 * BSZ);

    const int tid  = threadIdx.x;
    const int wid  = tid >> 5;
    const int lane = tid & 31;

    // ---- bid -> (ntile, kq, chunk base c0, chunk count nch) ----
    int ntile, kq, c0, nch;
    if (blockIdx.x < 288) {                 // long CTAs first (LPT dispatch)
        int u = blockIdx.x;
        ntile = 76 + u / 3;
        kq = u - 3 * (u / 3);
        c0  = (kq == 0) ? 0 : (kq == 1 ? 22 : 43);
        nch = (kq == 0) ? 22 : 21;
    } else {
        int v = blockIdx.x - 288;
        ntile = v >> 2;
        kq = v & 3;
        c0  = kq * 16;
        nch = 16;
    }
    const int n0 = ntile * NT;
    const int k0 = c0 * BK;

    // ---- build LUT (independent of xconv) ----
    {
        float lmin = __ldg(lmin_p);
        float lmax = __ldg(lmax_p);
        if (tid < 511) {
            int s = tid - 255;
            int mag = s < 0 ? -s : s;
            float w = 0.0f;
            if (s != 0) {
                float nrm = (255.0f - (float)mag) * (1.0f / 254.0f);
                w = expf(lmin + nrm * (lmax - lmin));
                if (s < 0) w = -w;
            }
            unsigned hb = (unsigned)__half_as_ushort(__float2half_rn(w));
            lut[tid] = hb | (hb << 16);
        }
    }
    __syncthreads();

    // ---- A fill geometry: 8 x 16B chunks per thread, swizzled ----
    int arow[8];
    uint32_t adoff[8];
    int asrc[8];
#pragma unroll
    for (int j = 0; j < 8; j++) {
        int idx = j * 512 + tid;          // 0..4095
        int row = idx >> 3;
        int c16 = idx & 7;
        arow[j] = row;
        asrc[j] = c16 * 8;
        adoff[j] = (uint32_t)(row * 128 + ((c16 ^ (row & 7)) << 4));
    }
    auto fillA = [&](int chunk, uint32_t aStage) {
        const __half* base = g_x + k0 + chunk * BK;
#pragma unroll
        for (int j = 0; j < 8; j++)
            CP16(aStage + adoff[j], base + (size_t)arow[j] * IN_ + asrc[j]);
        CP_COMMIT();
    };

    // ---- B dequant: 8 elems (one 16B chunk) per thread ----
    const int drow = tid >> 3;
    const int dc16 = tid & 7;
    const int* stp = stored + (size_t)(n0 + drow) * IN_ + k0 + dc16 * 8;
    const int* sgp = sign   + (size_t)(n0 + drow) * IN_ + k0 + dc16 * 8;
    const uint32_t bdoff = (uint32_t)(drow * 128 + ((dc16 ^ (drow & 7)) << 4));

    int4 st0, st1, sg0, sg1;
    auto bLDG = [&](int chunk) {
        const int4* a = reinterpret_cast<const int4*>(stp + chunk * BK);
        const int4* b = reinterpret_cast<const int4*>(sgp + chunk * BK);
        st0 = a[0]; st1 = a[1];
        sg0 = b[0]; sg1 = b[1];
    };
    auto bSTS = [&](uint32_t bStage) {
        unsigned l0 = lut[sg0.x * st0.x + 255];
        unsigned l1 = lut[sg0.y * st0.y + 255];
        unsigned l2 = lut[sg0.z * st0.z + 255];
        unsigned l3 = lut[sg0.w * st0.w + 255];
        unsigned l4 = lut[sg1.x * st1.x + 255];
        unsigned l5 = lut[sg1.y * st1.y + 255];
        unsigned l6 = lut[sg1.z * st1.z + 255];
        unsigned l7 = lut[sg1.w * st1.w + 255];
        uint32_t w0 = __byte_perm(l0, l1, 0x5410);
        uint32_t w1 = __byte_perm(l2, l3, 0x5410);
        uint32_t w2 = __byte_perm(l4, l5, 0x5410);
        uint32_t w3 = __byte_perm(l6, l7, 0x5410);
        asm volatile("st.shared.v4.b32 [%0], {%1,%2,%3,%4};"
                     :: "r"(bStage + bdoff), "r"(w0), "r"(w1), "r"(w2), "r"(w3)
                     : "memory");
    };

    // ---- ldmatrix offsets (16 warps: wm 0..7 x 64 rows, wn 0..1 x 32 cols) --
    const int wm = wid >> 1;
    const int wn = wid & 1;
    const int lr = lane & 7;
    const int lj = lane >> 3;
    uint32_t aOff[4][4], bOff[4][2];
#pragma unroll
    for (int ks = 0; ks < 4; ks++) {
#pragma unroll
        for (int mf = 0; mf < 4; mf++) {
            int row = wm * 64 + mf * 16 + lr + (lj & 1) * 8;
            int c16 = 2 * ks + (lj >> 1);
            aOff[ks][mf] = (uint32_t)(row * 128 + ((c16 ^ lr) << 4));
        }
#pragma unroll
        for (int nh = 0; nh < 2; nh++) {
            int nrow = wn * 32 + nh * 16 + lr + (lj >> 1) * 8;
            int c16  = 2 * ks + (lj & 1);
            bOff[ks][nh] = (uint32_t)(nrow * 128 + ((c16 ^ lr) << 4));
        }
    }

    float acc[4][4][4];
#pragma unroll
    for (int a = 0; a < 4; a++)
#pragma unroll
        for (int b = 0; b < 4; b++)
#pragma unroll
            for (int q = 0; q < 4; q++) acc[a][b][q] = 0.0f;

    // ---- prologue: B side first (independent of xconv), then wait, then A ---
    bLDG(0); bSTS(sB0);
    bLDG(1); bSTS(sB0 + BSZ);
    GRIDDEP_WAIT();                       // g_x ready (xconv complete)
    fillA(0, sA0);
    fillA(1, sA0 + ASZ);

    // ---- main loop (variable nch) ----
    int s = 0;
    for (int i = 0; i < nch; i++) {
        const int t = (s + 2 >= 3) ? s - 1 : s + 2;   // (i+2)%3
        const bool refill = (i + 2 < nch);

        // B LDG for chunk i+2: regs are dead, no smem touched -> issue BEFORE
        // the barrier so its latency overlaps the wait.
        if (refill) bLDG(i + 2);

        if (i < nch - 1) asm volatile("cp.async.wait_group 1;" ::: "memory");
        else             asm volatile("cp.async.wait_group 0;" ::: "memory");
        __syncthreads();

        if (refill) fillA(i + 2, sA0 + t * ASZ);

        uint32_t aBase = sA0 + s * ASZ;
        uint32_t bBase = sB0 + s * BSZ;
#pragma unroll
        for (int ks = 0; ks < 4; ks++) {
            uint32_t a_frag[4][4];
            uint32_t b_frag[4][2];
#pragma unroll
            for (int mf = 0; mf < 4; mf++)
                ldsm_x4(a_frag[mf], aBase + aOff[ks][mf]);
#pragma unroll
            for (int nh = 0; nh < 2; nh++) {
                uint32_t r[4];
                ldsm_x4(r, bBase + bOff[ks][nh]);
                b_frag[2 * nh][0]     = r[0];
                b_frag[2 * nh][1]     = r[1];
                b_frag[2 * nh + 1][0] = r[2];
                b_frag[2 * nh + 1][1] = r[3];
            }
#pragma unroll
            for (int mf = 0; mf < 4; mf++)
#pragma unroll
                for (int nf = 0; nf < 4; nf++)
                    mma16816(acc[mf][nf], a_frag[mf], b_frag[nf]);
        }

        if (refill) bSTS(sB0 + t * BSZ);

        if (++s == 3) s = 0;
    }

    // ---- epilogue: fp16 half2 stores into the partial plane ----
    __half* plane = g_part + (size_t)kq * PLANE;
    const int lq = lane >> 2;
    const int lp = lane & 3;
#pragma unroll
    for (int mf = 0; mf < 4; mf++) {
        int grow = wm * 64 + mf * 16 + lq;
#pragma unroll
        for (int nf = 0; nf < 4; nf++) {
            int gcol = n0 + wn * 32 + nf * 8 + 2 * lp;
            __half* p = plane + (size_t)grow * OUT_ + gcol;
            __half2 h0 = __floats2half2_rn(acc[mf][nf][0], acc[mf][nf][1]);
            __half2 h1 = __floats2half2_rn(acc[mf][nf][2], acc[mf][nf][3]);
            *reinterpret_cast<__half2*>(p)            = h0;
            *reinterpret_cast<__half2*>(p + 8 * OUT_) = h1;
        }
    }
}

// ---------------- reduce kernel: out = (sum(partials) + bias) * scale --------
// grid x block covers PLANE/8 exactly: 1 item (8 cols) per thread, no loop.
// Cols < COL_SPLIT3 have 4 partial planes; cols >= COL_SPLIT3 have 3.
__global__ void reduce_kernel(const float* __restrict__ bias,
                              const float* __restrict__ scale,
                              float* __restrict__ out) {
    int i = blockIdx.x * blockDim.x + threadIdx.x;
    size_t e = (size_t)i * 8;
    int col = (int)(e % OUT_);              // OUT_ % 8 == 0, never crosses a row
    // bias/scale are harness inputs -> load BEFORE waiting on fused.
    float4 b0 = __ldg(reinterpret_cast<const float4*>(bias + col));
    float4 b1 = __ldg(reinterpret_cast<const float4*>(bias + col + 4));
    float4 c0 = __ldg(reinterpret_cast<const float4*>(scale + col));
    float4 c1 = __ldg(reinterpret_cast<const float4*>(scale + col + 4));
    GRIDDEP_WAIT();                         // g_part ready (fused complete)
    uint4 q0 = __ldg(reinterpret_cast<const uint4*>(g_part + e));
    uint4 q1 = __ldg(reinterpret_cast<const uint4*>(g_part + PLANE + e));
    uint4 q2 = __ldg(reinterpret_cast<const uint4*>(g_part + 2 * PLANE + e));
    float r[8];
#pragma unroll
    for (int w = 0; w < 4; w++) {
        uint32_t u0 = (&q0.x)[w], u1 = (&q1.x)[w], u2 = (&q2.x)[w];
        float2 f0 = __half22float2(*reinterpret_cast<__half2*>(&u0));
        float2 f1 = __half22float2(*reinterpret_cast<__half2*>(&u1));
        float2 f2 = __half22float2(*reinterpret_cast<__half2*>(&u2));
        r[2 * w]     = f0.x + f1.x + f2.x;
        r[2 * w + 1] = f0.y + f1.y + f2.y;
    }
    if (col < COL_SPLIT3) {                 // 4-split tiles: add plane 3
        uint4 q3 = __ldg(reinterpret_cast<const uint4*>(g_part + 3 * PLANE + e));
#pragma unroll
        for (int w = 0; w < 4; w++) {
            uint32_t u3 = (&q3.x)[w];
            float2 f3 = __half22float2(*reinterpret_cast<__half2*>(&u3));
            r[2 * w]     += f3.x;
            r[2 * w + 1] += f3.y;
        }
    }
    float4 o0, o1;
    o0.x = (r[0] + b0.x) * c0.x;
    o0.y = (r[1] + b0.y) * c0.y;
    o0.z = (r[2] + b0.z) * c0.z;
    o0.w = (r[3] + b0.w) * c0.w;
    o1.x = (r[4] + b1.x) * c1.x;
    o1.y = (r[5] + b1.y) * c1.y;
    o1.z = (r[6] + b1.z) * c1.z;
    o1.w = (r[7] + b1.w) * c1.w;
    reinterpret_cast<float4*>(out + e)[0] = o0;
    reinterpret_cast<float4*>(out + e)[1] = o1;
}

// ---------------- launch -----------------------------------------------------
extern "C" void kernel_launch(void* const* d_in, const int* in_sizes, int n_in,
                              void* d_out, int out_size) {
    const float* x      = (const float*)d_in[0];
    const int*   stored = (const int*)d_in[1];
    const int*   sign   = (const int*)d_in[2];
    const float* lmin   = (const float*)d_in[3];
    const float* lmax   = (const float*)d_in[4];
    const float* scale  = (const float*)d_in[5];
    const float* bias   = (const float*)d_in[6];
    float* out = (float*)d_out;

    cudaFuncSetAttribute(fused_kernel, cudaFuncAttributeMaxDynamicSharedMemorySize,
                         (int)SMEM_REQ);

    xconv_kernel<<<1024, 256>>>(x);                       // 1024*256*2 = (B*IN)/4

    cudaLaunchAttribute attr[1];
    attr[0].id = cudaLaunchAttributeProgrammaticStreamSerialization;
    attr[0].val.programmaticStreamSerializationAllowed = 1;

    {   // fused: pre-launches while xconv drains; waits before touching g_x
        cudaLaunchConfig_t cfg = {};
        cfg.gridDim  = dim3(GRID_FUSED, 1, 1);
        cfg.blockDim = dim3(512, 1, 1);
        cfg.dynamicSmemBytes = SMEM_REQ;
        cfg.stream = 0;
        cfg.attrs = attr;
        cfg.numAttrs = 1;
        cudaLaunchKernelEx(&cfg, fused_kernel, stored, sign, lmin, lmax);
    }
    {   // reduce: pre-launches while fused drains; waits before reading g_part
        cudaLaunchConfig_t cfg = {};
        cfg.gridDim  = dim3(2752, 1, 1);                  // 2752*256 = PLANE/8
        cfg.blockDim = dim3(256, 1, 1);
        cfg.dynamicSmemBytes = 0;
        cfg.stream = 0;
        cfg.attrs = attr;
        cfg.numAttrs = 1;
        cudaLaunchKernelEx(&cfg, reduce_kernel, bias, scale, out);
    }
}